// round 12
// baseline (speedup 1.0000x reference)
#include <cuda_runtime.h>

#define BATCH  4
#define CCH    64
#define NPIX   16384
#define NHEADS 8
#define DHEAD  64
#define INNER  512
#define EPSN   1e-12f

typedef unsigned long long ull;

__device__ __forceinline__ ull splat2(float a) {
    unsigned u = __float_as_uint(a);
    ull r; asm("mov.b64 %0, {%1, %1};" : "=l"(r) : "r"(u)); return r;
}
__device__ __forceinline__ void fma2(ull& d, ull a, ull b) {
    asm("fma.rn.f32x2 %0, %1, %2, %0;" : "+l"(d) : "l"(a), "l"(b));
}
__device__ __forceinline__ float2 unpk(ull v) {
    unsigned lo, hi; asm("mov.b64 {%0, %1}, %2;" : "=r"(lo), "=r"(hi) : "l"(v));
    return make_float2(__uint_as_float(lo), __uint_as_float(hi));
}
__device__ __forceinline__ unsigned f2tf(float x) {
    unsigned r; asm("cvt.rna.tf32.f32 %0, %1;" : "=r"(r) : "f"(x)); return r;
}
__device__ __forceinline__ void mma8(float4& d, unsigned a0, unsigned a1, unsigned a2, unsigned a3,
                                     unsigned b0, unsigned b1) {
    asm volatile("mma.sync.aligned.m16n8k8.row.col.f32.tf32.tf32.f32 "
                 "{%0,%1,%2,%3}, {%4,%5,%6,%7}, {%8,%9}, {%0,%1,%2,%3};"
                 : "+f"(d.x), "+f"(d.y), "+f"(d.z), "+f"(d.w)
                 : "r"(a0), "r"(a1), "r"(a2), "r"(a3), "r"(b0), "r"(b1));
}

// ---------------- scratch ------------------------------------------------------
__device__ float    g_G[BATCH * CCH * CCH];   // zeroed at load; re-zeroed by attn
__device__ float    g_P[BATCH * CCH * CCH];   // zeroed at load; re-zeroed by out
__device__ unsigned g_cntG[BATCH];
__device__ unsigned g_cntP[BATCH];

// ---------------- K1: Gram via tf32 MMA + compensation ------------------------
// G_b += X_tile X_tile^T ; A and B fragments both come from the same x tile.
#define GXS 132     // lane bank = 4*gid + tig -> conflict-free fragment loads

__global__ void __launch_bounds__(256)
gram_kernel(const float* __restrict__ x) {
    __shared__ float xs[CCH * GXS];           // 33.8KB raw fp32 tile [64ch][128px]
    const int b     = blockIdx.x >> 7;
    const int chunk = blockIdx.x & 127;
    const int n0    = chunk * 128;
    const int tid   = threadIdx.x;

    const float* xb = x + (size_t)b * CCH * NPIX + n0;
    for (int i = tid; i < CCH * 32; i += 256) {
        int c = i >> 5, q = i & 31;
        float4 v = *(const float4*)(xb + (size_t)c * NPIX + q * 4);
        *(float4*)&xs[c * GXS + q * 4] = v;
    }
    __syncthreads();

    const int w    = tid >> 5;
    const int lane = tid & 31;
    const int gid  = lane >> 2;               // 0..7
    const int tig  = lane & 3;                // 0..3
    const int m0   = (w >> 1) * 16;
    const int nb0  = (w & 1) * 32;

    float4 acc[4];
    #pragma unroll
    for (int t = 0; t < 4; t++) acc[t] = make_float4(0.f, 0.f, 0.f, 0.f);

    for (int k0 = 0; k0 < 128; k0 += 8) {
        // A fragment (rows m0+gid / +8, cols k0+tig / +4), hi/lo split
        float ar0 = xs[(m0 + gid    ) * GXS + k0 + tig    ];
        float ar1 = xs[(m0 + gid + 8) * GXS + k0 + tig    ];
        float ar2 = xs[(m0 + gid    ) * GXS + k0 + tig + 4];
        float ar3 = xs[(m0 + gid + 8) * GXS + k0 + tig + 4];
        unsigned ah0 = f2tf(ar0), ah1 = f2tf(ar1), ah2 = f2tf(ar2), ah3 = f2tf(ar3);
        unsigned al0 = f2tf(ar0 - __uint_as_float(ah0));
        unsigned al1 = f2tf(ar1 - __uint_as_float(ah1));
        unsigned al2 = f2tf(ar2 - __uint_as_float(ah2));
        unsigned al3 = f2tf(ar3 - __uint_as_float(ah3));

        #pragma unroll
        for (int t = 0; t < 4; t++) {
            int nr = nb0 + t * 8 + gid;       // B col (= x channel row)
            float br0 = xs[nr * GXS + k0 + tig    ];
            float br1 = xs[nr * GXS + k0 + tig + 4];
            unsigned bh0 = f2tf(br0), bh1 = f2tf(br1);
            unsigned bl0 = f2tf(br0 - __uint_as_float(bh0));
            unsigned bl1 = f2tf(br1 - __uint_as_float(bh1));
            mma8(acc[t], ah0, ah1, ah2, ah3, bh0, bh1);
            mma8(acc[t], ah0, ah1, ah2, ah3, bl0, bl1);
            mma8(acc[t], al0, al1, al2, al3, bh0, bh1);
        }
    }

    float* Gb = g_G + b * CCH * CCH;
    #pragma unroll
    for (int t = 0; t < 4; t++) {
        int nc = nb0 + t * 8 + 2 * tig;
        atomicAdd(&Gb[(m0 + gid    ) * CCH + nc    ], acc[t].x);
        atomicAdd(&Gb[(m0 + gid    ) * CCH + nc + 1], acc[t].y);
        atomicAdd(&Gb[(m0 + gid + 8) * CCH + nc    ], acc[t].z);
        atomicAdd(&Gb[(m0 + gid + 8) * CCH + nc + 1], acc[t].w);
    }
}

// ---------------- K2: attention in channel space (R6 version, unchanged) ------
#define S68 68
#define OFF_G    0
#define OFF_WQ   (OFF_G  + CCH * 65)
#define OFF_WK   (OFF_WQ + CCH * CCH)
#define OFF_T1   (OFF_WK + CCH * CCH)
#define OFF_T2   (OFF_T1 + CCH * S68)
#define OFF_A    (OFF_T2 + CCH * S68)
#define OFF_WP   (OFF_A  + CCH * S68)
#define OFF_WVT  (OFF_WP + CCH * CCH)
#define OFF_QN   (OFF_WVT + CCH * S68)
#define OFF_KN   (OFF_QN + CCH)
#define ATTN_SMEM ((OFF_KN + CCH) * 4)

__global__ void __launch_bounds__(256)
attn_kernel(const float* __restrict__ Wq,
            const float* __restrict__ Wk,
            const float* __restrict__ Wv,
            const float* __restrict__ Wp,
            const float* __restrict__ rescale,
            float* __restrict__ attn_out) {
    extern __shared__ float sm[];
    float* Gs  = sm + OFF_G;
    float* Wqs = sm + OFF_WQ;
    float* Wks = sm + OFF_WK;
    float* T1  = sm + OFF_T1;
    float* T2  = sm + OFF_T2;
    float* As  = sm + OFF_A;
    float* Wps = sm + OFF_WP;
    float* WvT = sm + OFF_WVT;
    float* qn  = sm + OFF_QN;
    float* kn  = sm + OFF_KN;
    __shared__ int s_last;

    const int b   = blockIdx.x >> 3;
    const int h   = blockIdx.x & 7;
    const int tid = threadIdx.x;
    const int ti  = tid >> 4, tj = tid & 15;
    const int r0  = ti * 4,   e0 = tj * 4;

    for (int i = tid; i < CCH * CCH; i += 256) {
        int r = i >> 6, c = i & 63;
        Gs[r * 65 + c] = g_G[b * CCH * CCH + i];
        Wqs[i] = Wq[r * INNER + h * DHEAD + c];
        Wks[i] = Wk[r * INNER + h * DHEAD + c];
    }
    __syncthreads();
    if (tid == 0) s_last = (atomicAdd(&g_cntG[b], 1u) == NHEADS - 1) ? 1 : 0;

    // T1 = G @ Wq, T2 = G @ Wk
    {
        ull aq[4][2], ak[4][2];
        #pragma unroll
        for (int u = 0; u < 4; u++) { aq[u][0]=aq[u][1]=ak[u][0]=ak[u][1]=0ull; }

        for (int c = 0; c < CCH; c++) {
            float a0 = Gs[(r0 + 0) * 65 + c], a1 = Gs[(r0 + 1) * 65 + c];
            float a2 = Gs[(r0 + 2) * 65 + c], a3 = Gs[(r0 + 3) * 65 + c];
            ulonglong2 bq = *(const ulonglong2*)&Wqs[c * CCH + e0];
            ulonglong2 bk = *(const ulonglong2*)&Wks[c * CCH + e0];
            ull s0 = splat2(a0), s1 = splat2(a1), s2 = splat2(a2), s3 = splat2(a3);
            fma2(aq[0][0], s0, bq.x); fma2(aq[0][1], s0, bq.y);
            fma2(aq[1][0], s1, bq.x); fma2(aq[1][1], s1, bq.y);
            fma2(aq[2][0], s2, bq.x); fma2(aq[2][1], s2, bq.y);
            fma2(aq[3][0], s3, bq.x); fma2(aq[3][1], s3, bq.y);
            fma2(ak[0][0], s0, bk.x); fma2(ak[0][1], s0, bk.y);
            fma2(ak[1][0], s1, bk.x); fma2(ak[1][1], s1, bk.y);
            fma2(ak[2][0], s2, bk.x); fma2(ak[2][1], s2, bk.y);
            fma2(ak[3][0], s3, bk.x); fma2(ak[3][1], s3, bk.y);
        }
        #pragma unroll
        for (int u = 0; u < 4; u++) {
            float2 q0 = unpk(aq[u][0]), q1 = unpk(aq[u][1]);
            float2 k0 = unpk(ak[u][0]), k1 = unpk(ak[u][1]);
            *(float4*)&T1[(r0 + u) * S68 + e0] = make_float4(q0.x, q0.y, q1.x, q1.y);
            *(float4*)&T2[(r0 + u) * S68 + e0] = make_float4(k0.x, k0.y, k1.x, k1.y);
        }
    }
    __syncthreads();

    if (tid < 128) {
        const int e = tid & 63;
        const float* W = (tid < 64) ? Wqs : Wks;
        const float* T = (tid < 64) ? T1  : T2;
        float s = 0.f;
        #pragma unroll 8
        for (int c = 0; c < CCH; c++) s = fmaf(W[c * CCH + e], T[c * S68 + e], s);
        ((tid < 64) ? qn : kn)[e] = 1.f / fmaxf(sqrtf(s), EPSN);
    }

    // A_raw = T2^T @ Wq
    {
        ull acc[4][2];
        #pragma unroll
        for (int u = 0; u < 4; u++) { acc[u][0] = acc[u][1] = 0ull; }
        for (int c = 0; c < CCH; c++) {
            float4 av = *(const float4*)&T2[c * S68 + r0];
            ulonglong2 bv = *(const ulonglong2*)&Wqs[c * CCH + e0];
            ull s0 = splat2(av.x), s1 = splat2(av.y), s2 = splat2(av.z), s3 = splat2(av.w);
            fma2(acc[0][0], s0, bv.x); fma2(acc[0][1], s0, bv.y);
            fma2(acc[1][0], s1, bv.x); fma2(acc[1][1], s1, bv.y);
            fma2(acc[2][0], s2, bv.x); fma2(acc[2][1], s2, bv.y);
            fma2(acc[3][0], s3, bv.x); fma2(acc[3][1], s3, bv.y);
        }
        #pragma unroll
        for (int u = 0; u < 4; u++) {
            float2 p0 = unpk(acc[u][0]), p1 = unpk(acc[u][1]);
            *(float4*)&As[(r0 + u) * S68 + e0] = make_float4(p0.x, p0.y, p1.x, p1.y);
        }
    }

    for (int i = tid; i < CCH * CCH; i += 256) {
        int r = i >> 6, c = i & 63;
        Wps[i] = Wp[(h * DHEAD + r) * CCH + c];
        WvT[c * S68 + r] = Wv[r * INNER + h * DHEAD + c];
    }
    __syncthreads();

    // scaled softmax (4 lanes per row)
    {
        const int d = tid >> 2, g = tid & 3;
        float* row = As + d * S68;
        const float sk = kn[d] * rescale[h];
        float vals[16];
        float mx = -1e30f;
        #pragma unroll
        for (int k = 0; k < 16; k++) {
            int e = g + 4 * k;
            float v = row[e] * sk * qn[e];
            vals[k] = v;
            mx = fmaxf(mx, v);
        }
        mx = fmaxf(mx, __shfl_xor_sync(0xffffffffu, mx, 1));
        mx = fmaxf(mx, __shfl_xor_sync(0xffffffffu, mx, 2));
        float s = 0.f;
        #pragma unroll
        for (int k = 0; k < 16; k++) { vals[k] = __expf(vals[k] - mx); s += vals[k]; }
        s += __shfl_xor_sync(0xffffffffu, s, 1);
        s += __shfl_xor_sync(0xffffffffu, s, 2);
        float inv = 1.f / s;
        #pragma unroll
        for (int k = 0; k < 16; k++) row[g + 4 * k] = vals[k] * inv;
    }
    __syncthreads();

    float* ao = attn_out + (size_t)(b * NHEADS + h) * DHEAD * DHEAD;
    for (int i = tid; i < CCH * CCH; i += 256)
        ao[i] = As[(i >> 6) * S68 + (i & 63)];

    // M[e][c] = sum_d A[d][e] * Wp[d][c]  -> T1
    {
        ull acc[4][2];
        #pragma unroll
        for (int u = 0; u < 4; u++) { acc[u][0] = acc[u][1] = 0ull; }
        for (int d = 0; d < CCH; d++) {
            float4 av = *(const float4*)&As[d * S68 + r0];
            ulonglong2 bv = *(const ulonglong2*)&Wps[d * CCH + e0];
            ull s0 = splat2(av.x), s1 = splat2(av.y), s2 = splat2(av.z), s3 = splat2(av.w);
            fma2(acc[0][0], s0, bv.x); fma2(acc[0][1], s0, bv.y);
            fma2(acc[1][0], s1, bv.x); fma2(acc[1][1], s1, bv.y);
            fma2(acc[2][0], s2, bv.x); fma2(acc[2][1], s2, bv.y);
            fma2(acc[3][0], s3, bv.x); fma2(acc[3][1], s3, bv.y);
        }
        #pragma unroll
        for (int u = 0; u < 4; u++) {
            float2 p0 = unpk(acc[u][0]), p1 = unpk(acc[u][1]);
            *(float4*)&T1[(r0 + u) * S68 + e0] = make_float4(p0.x, p0.y, p1.x, p1.y);
        }
    }
    __syncthreads();

    // P[cin][c] += Wv[cin][:] @ M[:][c]
    {
        ull acc[4][2];
        #pragma unroll
        for (int u = 0; u < 4; u++) { acc[u][0] = acc[u][1] = 0ull; }
        for (int e = 0; e < CCH; e++) {
            float4 av = *(const float4*)&WvT[e * S68 + r0];
            ulonglong2 bv = *(const ulonglong2*)&T1[e * S68 + e0];
            ull s0 = splat2(av.x), s1 = splat2(av.y), s2 = splat2(av.z), s3 = splat2(av.w);
            fma2(acc[0][0], s0, bv.x); fma2(acc[0][1], s0, bv.y);
            fma2(acc[1][0], s1, bv.x); fma2(acc[1][1], s1, bv.y);
            fma2(acc[2][0], s2, bv.x); fma2(acc[2][1], s2, bv.y);
            fma2(acc[3][0], s3, bv.x); fma2(acc[3][1], s3, bv.y);
        }
        float* Pb = g_P + b * CCH * CCH;
        #pragma unroll
        for (int u = 0; u < 4; u++) {
            float2 p0 = unpk(acc[u][0]), p1 = unpk(acc[u][1]);
            atomicAdd(&Pb[(r0 + u) * CCH + e0 + 0], p0.x);
            atomicAdd(&Pb[(r0 + u) * CCH + e0 + 1], p0.y);
            atomicAdd(&Pb[(r0 + u) * CCH + e0 + 2], p1.x);
            atomicAdd(&Pb[(r0 + u) * CCH + e0 + 3], p1.y);
        }
    }

    __syncthreads();
    if (s_last) {
        for (int i = tid; i < CCH * CCH; i += 256) g_G[b * CCH * CCH + i] = 0.f;
        if (tid == 0) g_cntG[b] = 0u;
    }
}

// ---------------- K3: out = X @ P + bp via tf32 MMA + compensation ------------
#define OXS 136     // B frag lane bank = 8*tig + gid -> conflict-free
#define OPS 72      // A frag lane bank = 8*tig + gid -> conflict-free
#define OUT_SMEM ((CCH * OXS + CCH * OPS + CCH) * 4)

__global__ void __launch_bounds__(256)
out_kernel(const float* __restrict__ x,
           const float* __restrict__ bp,
           float* __restrict__ out) {
    extern __shared__ float sm[];
    float* xs  = sm;                           // [64 j][136] raw x tile (j=in-ch, px)
    float* Ps  = sm + CCH * OXS;               // [64 j][72]  raw P  (P[j][c])
    float* bps = Ps + CCH * OPS;
    __shared__ int s_last;

    const int b     = blockIdx.x >> 7;
    const int chunk = blockIdx.x & 127;
    const int n0    = chunk * 128;
    const int tid   = threadIdx.x;

    const float* Pg = g_P + b * CCH * CCH;
    for (int i = tid; i < CCH * CCH / 4; i += 256) {
        int r = i >> 4, c4 = i & 15;
        float4 v = *(const float4*)(Pg + r * CCH + c4 * 4);
        *(float4*)&Ps[r * OPS + c4 * 4] = v;
    }
    if (tid < CCH) bps[tid] = bp[tid];

    const float* xb = x + (size_t)b * CCH * NPIX + n0;
    for (int i = tid; i < CCH * 32; i += 256) {
        int c = i >> 5, q = i & 31;
        float4 v = *(const float4*)(xb + (size_t)c * NPIX + q * 4);
        *(float4*)&xs[c * OXS + q * 4] = v;
    }
    __syncthreads();
    if (tid == 0) s_last = (atomicAdd(&g_cntP[b], 1u) == 127u) ? 1 : 0;

    const int w    = tid >> 5;
    const int lane = tid & 31;
    const int gid  = lane >> 2;
    const int tig  = lane & 3;
    const int m0   = (w >> 1) * 16;            // out-channel tile
    const int nb0  = (w & 1) * 64;             // pixel half

    float4 acc[8];
    #pragma unroll
    for (int t = 0; t < 8; t++) acc[t] = make_float4(0.f, 0.f, 0.f, 0.f);

    #pragma unroll
    for (int k0 = 0; k0 < CCH; k0 += 8) {
        // A fragment from P^T: A[m][k] = P[k][m]
        float pr0 = Ps[(k0 + tig    ) * OPS + m0 + gid    ];
        float pr1 = Ps[(k0 + tig    ) * OPS + m0 + gid + 8];
        float pr2 = Ps[(k0 + tig + 4) * OPS + m0 + gid    ];
        float pr3 = Ps[(k0 + tig + 4) * OPS + m0 + gid + 8];
        unsigned ah0 = f2tf(pr0), ah1 = f2tf(pr1), ah2 = f2tf(pr2), ah3 = f2tf(pr3);
        unsigned al0 = f2tf(pr0 - __uint_as_float(ah0));
        unsigned al1 = f2tf(pr1 - __uint_as_float(ah1));
        unsigned al2 = f2tf(pr2 - __uint_as_float(ah2));
        unsigned al3 = f2tf(pr3 - __uint_as_float(ah3));

        #pragma unroll
        for (int t = 0; t < 8; t++) {
            int nn = nb0 + t * 8 + gid;
            float xr0 = xs[(k0 + tig    ) * OXS + nn];
            float xr1 = xs[(k0 + tig + 4) * OXS + nn];
            unsigned bh0 = f2tf(xr0), bh1 = f2tf(xr1);
            unsigned bl0 = f2tf(xr0 - __uint_as_float(bh0));
            unsigned bl1 = f2tf(xr1 - __uint_as_float(bh1));
            mma8(acc[t], ah0, ah1, ah2, ah3, bh0, bh1);
            mma8(acc[t], ah0, ah1, ah2, ah3, bl0, bl1);
            mma8(acc[t], al0, al1, al2, al3, bh0, bh1);
        }
    }

    const float bias0 = bps[m0 + gid];
    const float bias1 = bps[m0 + gid + 8];
    float* o0 = out + ((size_t)(b * CCH + m0 + gid    )) * NPIX + n0;
    float* o1 = out + ((size_t)(b * CCH + m0 + gid + 8)) * NPIX + n0;
    #pragma unroll
    for (int t = 0; t < 8; t++) {
        int nc = nb0 + t * 8 + 2 * tig;
        *(float2*)(o0 + nc) = make_float2(acc[t].x + bias0, acc[t].y + bias0);
        *(float2*)(o1 + nc) = make_float2(acc[t].z + bias1, acc[t].w + bias1);
    }

    __syncthreads();
    if (s_last) {
        for (int i = tid; i < CCH * CCH; i += 256) g_P[b * CCH * CCH + i] = 0.f;
        if (tid == 0) g_cntP[b] = 0u;
    }
}

// ---------------- launch ------------------------------------------------------
extern "C" void kernel_launch(void* const* d_in, const int* in_sizes, int n_in,
                              void* d_out, int out_size) {
    const float* x       = (const float*)d_in[0];
    const float* Wq      = (const float*)d_in[1];
    const float* Wk      = (const float*)d_in[2];
    const float* Wv      = (const float*)d_in[3];
    const float* Wp      = (const float*)d_in[4];
    const float* bp      = (const float*)d_in[5];
    const float* rescale = (const float*)d_in[6];

    float* out      = (float*)d_out;
    float* attn_out = out + (size_t)out_size - (size_t)BATCH * NHEADS * DHEAD * DHEAD;

    cudaFuncSetAttribute(attn_kernel, cudaFuncAttributeMaxDynamicSharedMemorySize, ATTN_SMEM);
    cudaFuncSetAttribute(out_kernel,  cudaFuncAttributeMaxDynamicSharedMemorySize, OUT_SMEM);

    gram_kernel<<<BATCH * 128, 256>>>(x);
    attn_kernel<<<BATCH * NHEADS, 256, ATTN_SMEM>>>(Wq, Wk, Wv, Wp, rescale, attn_out);
    out_kernel<<<BATCH * 128, 256, OUT_SMEM>>>(x, bp, out);
}

// round 13
// speedup vs baseline: 1.0040x; 1.0040x over previous
#include <cuda_runtime.h>

#define BATCH  4
#define CCH    64
#define NPIX   16384
#define NHEADS 8
#define DHEAD  64
#define INNER  512
#define EPSN   1e-12f

typedef unsigned long long ull;

__device__ __forceinline__ ull splat2(float a) {
    unsigned u = __float_as_uint(a);
    ull r; asm("mov.b64 %0, {%1, %1};" : "=l"(r) : "r"(u)); return r;
}
__device__ __forceinline__ void fma2(ull& d, ull a, ull b) {
    asm("fma.rn.f32x2 %0, %1, %2, %0;" : "+l"(d) : "l"(a), "l"(b));
}
__device__ __forceinline__ float2 unpk(ull v) {
    unsigned lo, hi; asm("mov.b64 {%0, %1}, %2;" : "=r"(lo), "=r"(hi) : "l"(v));
    return make_float2(__uint_as_float(lo), __uint_as_float(hi));
}
__device__ __forceinline__ float f2tf(float x) {
    unsigned r; asm("cvt.rna.tf32.f32 %0, %1;" : "=r"(r) : "f"(x));
    return __uint_as_float(r);
}
// split x into tf32 hi + tf32-rounded residual lo
__device__ __forceinline__ void tfsplit(float x, float& h, float& l) {
    h = f2tf(x);
    l = f2tf(x - h);
}
__device__ __forceinline__ void mma8(float4& d, float a0, float a1, float a2, float a3,
                                     float b0, float b1) {
    asm volatile("mma.sync.aligned.m16n8k8.row.col.f32.tf32.tf32.f32 "
                 "{%0,%1,%2,%3}, {%4,%5,%6,%7}, {%8,%9}, {%0,%1,%2,%3};"
                 : "+f"(d.x), "+f"(d.y), "+f"(d.z), "+f"(d.w)
                 : "r"(__float_as_uint(a0)), "r"(__float_as_uint(a1)),
                   "r"(__float_as_uint(a2)), "r"(__float_as_uint(a3)),
                   "r"(__float_as_uint(b0)), "r"(__float_as_uint(b1)));
}

// ---------------- scratch ------------------------------------------------------
__device__ float    g_G[BATCH * CCH * CCH];   // zeroed at load; re-zeroed by attn
__device__ float    g_P[BATCH * CCH * CCH];   // zeroed at load; re-zeroed by out
__device__ unsigned g_cntG[BATCH];
__device__ unsigned g_cntP[BATCH];

// ---------------- K1: Gram via tf32 MMA, pre-converted hi/lo tiles ------------
#define GXS 132
#define GRAM_SMEM (2 * CCH * GXS * 4)

__global__ void __launch_bounds__(256)
gram_kernel(const float* __restrict__ x) {
    extern __shared__ float smg[];
    float* his = smg;                          // [64][132] tf32-hi
    float* los = smg + CCH * GXS;              // [64][132] tf32-lo
    const int b     = blockIdx.x >> 7;
    const int chunk = blockIdx.x & 127;
    const int n0    = chunk * 128;
    const int tid   = threadIdx.x;

    const float* xb = x + (size_t)b * CCH * NPIX + n0;
    for (int i = tid; i < CCH * 32; i += 256) {
        int c = i >> 5, q = i & 31;
        float4 v = *(const float4*)(xb + (size_t)c * NPIX + q * 4);
        float4 h, l;
        tfsplit(v.x, h.x, l.x); tfsplit(v.y, h.y, l.y);
        tfsplit(v.z, h.z, l.z); tfsplit(v.w, h.w, l.w);
        *(float4*)&his[c * GXS + q * 4] = h;
        *(float4*)&los[c * GXS + q * 4] = l;
    }
    __syncthreads();

    const int w    = tid >> 5;
    const int lane = tid & 31;
    const int gid  = lane >> 2;
    const int tig  = lane & 3;
    const int m0   = (w >> 1) * 16;
    const int nb0  = (w & 1) * 32;

    float4 acc[4];
    #pragma unroll
    for (int t = 0; t < 4; t++) acc[t] = make_float4(0.f, 0.f, 0.f, 0.f);

    for (int k0 = 0; k0 < 128; k0 += 8) {
        const int ra = (m0 + gid) * GXS + k0 + tig;
        float ah0 = his[ra], ah1 = his[ra + 8 * GXS], ah2 = his[ra + 4], ah3 = his[ra + 8 * GXS + 4];
        float al0 = los[ra], al1 = los[ra + 8 * GXS], al2 = los[ra + 4], al3 = los[ra + 8 * GXS + 4];
        #pragma unroll
        for (int t = 0; t < 4; t++) {
            const int rb = (nb0 + t * 8 + gid) * GXS + k0 + tig;
            float bh0 = his[rb], bh1 = his[rb + 4];
            float bl0 = los[rb], bl1 = los[rb + 4];
            mma8(acc[t], ah0, ah1, ah2, ah3, bh0, bh1);
            mma8(acc[t], ah0, ah1, ah2, ah3, bl0, bl1);
            mma8(acc[t], al0, al1, al2, al3, bh0, bh1);
        }
    }

    float* Gb = g_G + b * CCH * CCH;
    #pragma unroll
    for (int t = 0; t < 4; t++) {
        int nc = nb0 + t * 8 + 2 * tig;
        atomicAdd(&Gb[(m0 + gid    ) * CCH + nc    ], acc[t].x);
        atomicAdd(&Gb[(m0 + gid    ) * CCH + nc + 1], acc[t].y);
        atomicAdd(&Gb[(m0 + gid + 8) * CCH + nc    ], acc[t].z);
        atomicAdd(&Gb[(m0 + gid + 8) * CCH + nc + 1], acc[t].w);
    }
}

// ---------------- K2: attention in channel space (R6 version, unchanged) ------
#define S68 68
#define OFF_G    0
#define OFF_WQ   (OFF_G  + CCH * 65)
#define OFF_WK   (OFF_WQ + CCH * CCH)
#define OFF_T1   (OFF_WK + CCH * CCH)
#define OFF_T2   (OFF_T1 + CCH * S68)
#define OFF_A    (OFF_T2 + CCH * S68)
#define OFF_WP   (OFF_A  + CCH * S68)
#define OFF_WVT  (OFF_WP + CCH * CCH)
#define OFF_QN   (OFF_WVT + CCH * S68)
#define OFF_KN   (OFF_QN + CCH)
#define ATTN_SMEM ((OFF_KN + CCH) * 4)

__global__ void __launch_bounds__(256)
attn_kernel(const float* __restrict__ Wq,
            const float* __restrict__ Wk,
            const float* __restrict__ Wv,
            const float* __restrict__ Wp,
            const float* __restrict__ rescale,
            float* __restrict__ attn_out) {
    extern __shared__ float sm[];
    float* Gs  = sm + OFF_G;
    float* Wqs = sm + OFF_WQ;
    float* Wks = sm + OFF_WK;
    float* T1  = sm + OFF_T1;
    float* T2  = sm + OFF_T2;
    float* As  = sm + OFF_A;
    float* Wps = sm + OFF_WP;
    float* WvT = sm + OFF_WVT;
    float* qn  = sm + OFF_QN;
    float* kn  = sm + OFF_KN;
    __shared__ int s_last;

    const int b   = blockIdx.x >> 3;
    const int h   = blockIdx.x & 7;
    const int tid = threadIdx.x;
    const int ti  = tid >> 4, tj = tid & 15;
    const int r0  = ti * 4,   e0 = tj * 4;

    for (int i = tid; i < CCH * CCH; i += 256) {
        int r = i >> 6, c = i & 63;
        Gs[r * 65 + c] = g_G[b * CCH * CCH + i];
        Wqs[i] = Wq[r * INNER + h * DHEAD + c];
        Wks[i] = Wk[r * INNER + h * DHEAD + c];
    }
    __syncthreads();
    if (tid == 0) s_last = (atomicAdd(&g_cntG[b], 1u) == NHEADS - 1) ? 1 : 0;

    // T1 = G @ Wq, T2 = G @ Wk
    {
        ull aq[4][2], ak[4][2];
        #pragma unroll
        for (int u = 0; u < 4; u++) { aq[u][0]=aq[u][1]=ak[u][0]=ak[u][1]=0ull; }

        for (int c = 0; c < CCH; c++) {
            float a0 = Gs[(r0 + 0) * 65 + c], a1 = Gs[(r0 + 1) * 65 + c];
            float a2 = Gs[(r0 + 2) * 65 + c], a3 = Gs[(r0 + 3) * 65 + c];
            ulonglong2 bq = *(const ulonglong2*)&Wqs[c * CCH + e0];
            ulonglong2 bk = *(const ulonglong2*)&Wks[c * CCH + e0];
            ull s0 = splat2(a0), s1 = splat2(a1), s2 = splat2(a2), s3 = splat2(a3);
            fma2(aq[0][0], s0, bq.x); fma2(aq[0][1], s0, bq.y);
            fma2(aq[1][0], s1, bq.x); fma2(aq[1][1], s1, bq.y);
            fma2(aq[2][0], s2, bq.x); fma2(aq[2][1], s2, bq.y);
            fma2(aq[3][0], s3, bq.x); fma2(aq[3][1], s3, bq.y);
            fma2(ak[0][0], s0, bk.x); fma2(ak[0][1], s0, bk.y);
            fma2(ak[1][0], s1, bk.x); fma2(ak[1][1], s1, bk.y);
            fma2(ak[2][0], s2, bk.x); fma2(ak[2][1], s2, bk.y);
            fma2(ak[3][0], s3, bk.x); fma2(ak[3][1], s3, bk.y);
        }
        #pragma unroll
        for (int u = 0; u < 4; u++) {
            float2 q0 = unpk(aq[u][0]), q1 = unpk(aq[u][1]);
            float2 k0 = unpk(ak[u][0]), k1 = unpk(ak[u][1]);
            *(float4*)&T1[(r0 + u) * S68 + e0] = make_float4(q0.x, q0.y, q1.x, q1.y);
            *(float4*)&T2[(r0 + u) * S68 + e0] = make_float4(k0.x, k0.y, k1.x, k1.y);
        }
    }
    __syncthreads();

    if (tid < 128) {
        const int e = tid & 63;
        const float* W = (tid < 64) ? Wqs : Wks;
        const float* T = (tid < 64) ? T1  : T2;
        float s = 0.f;
        #pragma unroll 8
        for (int c = 0; c < CCH; c++) s = fmaf(W[c * CCH + e], T[c * S68 + e], s);
        ((tid < 64) ? qn : kn)[e] = 1.f / fmaxf(sqrtf(s), EPSN);
    }

    // A_raw = T2^T @ Wq
    {
        ull acc[4][2];
        #pragma unroll
        for (int u = 0; u < 4; u++) { acc[u][0] = acc[u][1] = 0ull; }
        for (int c = 0; c < CCH; c++) {
            float4 av = *(const float4*)&T2[c * S68 + r0];
            ulonglong2 bv = *(const ulonglong2*)&Wqs[c * CCH + e0];
            ull s0 = splat2(av.x), s1 = splat2(av.y), s2 = splat2(av.z), s3 = splat2(av.w);
            fma2(acc[0][0], s0, bv.x); fma2(acc[0][1], s0, bv.y);
            fma2(acc[1][0], s1, bv.x); fma2(acc[1][1], s1, bv.y);
            fma2(acc[2][0], s2, bv.x); fma2(acc[2][1], s2, bv.y);
            fma2(acc[3][0], s3, bv.x); fma2(acc[3][1], s3, bv.y);
        }
        #pragma unroll
        for (int u = 0; u < 4; u++) {
            float2 p0 = unpk(acc[u][0]), p1 = unpk(acc[u][1]);
            *(float4*)&As[(r0 + u) * S68 + e0] = make_float4(p0.x, p0.y, p1.x, p1.y);
        }
    }

    for (int i = tid; i < CCH * CCH; i += 256) {
        int r = i >> 6, c = i & 63;
        Wps[i] = Wp[(h * DHEAD + r) * CCH + c];
        WvT[c * S68 + r] = Wv[r * INNER + h * DHEAD + c];
    }
    __syncthreads();

    // scaled softmax (4 lanes per row)
    {
        const int d = tid >> 2, g = tid & 3;
        float* row = As + d * S68;
        const float sk = kn[d] * rescale[h];
        float vals[16];
        float mx = -1e30f;
        #pragma unroll
        for (int k = 0; k < 16; k++) {
            int e = g + 4 * k;
            float v = row[e] * sk * qn[e];
            vals[k] = v;
            mx = fmaxf(mx, v);
        }
        mx = fmaxf(mx, __shfl_xor_sync(0xffffffffu, mx, 1));
        mx = fmaxf(mx, __shfl_xor_sync(0xffffffffu, mx, 2));
        float s = 0.f;
        #pragma unroll
        for (int k = 0; k < 16; k++) { vals[k] = __expf(vals[k] - mx); s += vals[k]; }
        s += __shfl_xor_sync(0xffffffffu, s, 1);
        s += __shfl_xor_sync(0xffffffffu, s, 2);
        float inv = 1.f / s;
        #pragma unroll
        for (int k = 0; k < 16; k++) row[g + 4 * k] = vals[k] * inv;
    }
    __syncthreads();

    float* ao = attn_out + (size_t)(b * NHEADS + h) * DHEAD * DHEAD;
    for (int i = tid; i < CCH * CCH; i += 256)
        ao[i] = As[(i >> 6) * S68 + (i & 63)];

    // M[e][c] = sum_d A[d][e] * Wp[d][c]  -> T1
    {
        ull acc[4][2];
        #pragma unroll
        for (int u = 0; u < 4; u++) { acc[u][0] = acc[u][1] = 0ull; }
        for (int d = 0; d < CCH; d++) {
            float4 av = *(const float4*)&As[d * S68 + r0];
            ulonglong2 bv = *(const ulonglong2*)&Wps[d * CCH + e0];
            ull s0 = splat2(av.x), s1 = splat2(av.y), s2 = splat2(av.z), s3 = splat2(av.w);
            fma2(acc[0][0], s0, bv.x); fma2(acc[0][1], s0, bv.y);
            fma2(acc[1][0], s1, bv.x); fma2(acc[1][1], s1, bv.y);
            fma2(acc[2][0], s2, bv.x); fma2(acc[2][1], s2, bv.y);
            fma2(acc[3][0], s3, bv.x); fma2(acc[3][1], s3, bv.y);
        }
        #pragma unroll
        for (int u = 0; u < 4; u++) {
            float2 p0 = unpk(acc[u][0]), p1 = unpk(acc[u][1]);
            *(float4*)&T1[(r0 + u) * S68 + e0] = make_float4(p0.x, p0.y, p1.x, p1.y);
        }
    }
    __syncthreads();

    // P[cin][c] += Wv[cin][:] @ M[:][c]
    {
        ull acc[4][2];
        #pragma unroll
        for (int u = 0; u < 4; u++) { acc[u][0] = acc[u][1] = 0ull; }
        for (int e = 0; e < CCH; e++) {
            float4 av = *(const float4*)&WvT[e * S68 + r0];
            ulonglong2 bv = *(const ulonglong2*)&T1[e * S68 + e0];
            ull s0 = splat2(av.x), s1 = splat2(av.y), s2 = splat2(av.z), s3 = splat2(av.w);
            fma2(acc[0][0], s0, bv.x); fma2(acc[0][1], s0, bv.y);
            fma2(acc[1][0], s1, bv.x); fma2(acc[1][1], s1, bv.y);
            fma2(acc[2][0], s2, bv.x); fma2(acc[2][1], s2, bv.y);
            fma2(acc[3][0], s3, bv.x); fma2(acc[3][1], s3, bv.y);
        }
        float* Pb = g_P + b * CCH * CCH;
        #pragma unroll
        for (int u = 0; u < 4; u++) {
            float2 p0 = unpk(acc[u][0]), p1 = unpk(acc[u][1]);
            atomicAdd(&Pb[(r0 + u) * CCH + e0 + 0], p0.x);
            atomicAdd(&Pb[(r0 + u) * CCH + e0 + 1], p0.y);
            atomicAdd(&Pb[(r0 + u) * CCH + e0 + 2], p1.x);
            atomicAdd(&Pb[(r0 + u) * CCH + e0 + 3], p1.y);
        }
    }

    __syncthreads();
    if (s_last) {
        for (int i = tid; i < CCH * CCH; i += 256) g_G[b * CCH * CCH + i] = 0.f;
        if (tid == 0) g_cntG[b] = 0u;
    }
}

// ---------------- K3: out = X @ P + bp via tf32 MMA, pre-converted ------------
#define ONPX 64
#define OXS  72
#define OPS  72
#define OFF_XH 0
#define OFF_XL (CCH * OXS)
#define OFF_PH (2 * CCH * OXS)
#define OFF_PL (OFF_PH + CCH * OPS)
#define OFF_BP (OFF_PL + CCH * OPS)
#define OUT_SMEM ((OFF_BP + CCH) * 4)

__global__ void __launch_bounds__(256)
out_kernel(const float* __restrict__ x,
           const float* __restrict__ bp,
           float* __restrict__ out) {
    extern __shared__ float smo[];
    float* xhi = smo + OFF_XH;                 // [64 k][72 px]
    float* xlo = smo + OFF_XL;
    float* phi = smo + OFF_PH;                 // [64 k][72 c]  (P[k][c])
    float* plo = smo + OFF_PL;
    float* bps = smo + OFF_BP;
    __shared__ int s_last;

    const int b     = blockIdx.x >> 8;
    const int chunk = blockIdx.x & 255;
    const int n0    = chunk * ONPX;
    const int tid   = threadIdx.x;

    const float* Pg = g_P + b * CCH * CCH;
    for (int i = tid; i < CCH * CCH / 4; i += 256) {
        int r = i >> 4, c4 = i & 15;
        float4 v = *(const float4*)(Pg + r * CCH + c4 * 4);
        float4 h, l;
        tfsplit(v.x, h.x, l.x); tfsplit(v.y, h.y, l.y);
        tfsplit(v.z, h.z, l.z); tfsplit(v.w, h.w, l.w);
        *(float4*)&phi[r * OPS + c4 * 4] = h;
        *(float4*)&plo[r * OPS + c4 * 4] = l;
    }
    if (tid < CCH) bps[tid] = bp[tid];

    const float* xb = x + (size_t)b * CCH * NPIX + n0;
    for (int i = tid; i < CCH * (ONPX / 4); i += 256) {
        int c = i >> 4, q = i & 15;
        float4 v = *(const float4*)(xb + (size_t)c * NPIX + q * 4);
        float4 h, l;
        tfsplit(v.x, h.x, l.x); tfsplit(v.y, h.y, l.y);
        tfsplit(v.z, h.z, l.z); tfsplit(v.w, h.w, l.w);
        *(float4*)&xhi[c * OXS + q * 4] = h;
        *(float4*)&xlo[c * OXS + q * 4] = l;
    }
    __syncthreads();
    if (tid == 0) s_last = (atomicAdd(&g_cntP[b], 1u) == 255u) ? 1 : 0;

    const int w    = tid >> 5;
    const int lane = tid & 31;
    const int gid  = lane >> 2;
    const int tig  = lane & 3;
    const int m0   = (w >> 1) * 16;            // out-channel tile
    const int nb0  = (w & 1) * 32;             // pixel half

    float4 acc[4];
    #pragma unroll
    for (int t = 0; t < 4; t++) acc[t] = make_float4(0.f, 0.f, 0.f, 0.f);

    #pragma unroll
    for (int k0 = 0; k0 < CCH; k0 += 8) {
        // A fragment from P^T: A[m][k] = P[k][m]
        const int ra = (k0 + tig) * OPS + m0 + gid;
        float ah0 = phi[ra], ah1 = phi[ra + 8], ah2 = phi[ra + 4 * OPS], ah3 = phi[ra + 4 * OPS + 8];
        float al0 = plo[ra], al1 = plo[ra + 8], al2 = plo[ra + 4 * OPS], al3 = plo[ra + 4 * OPS + 8];
        #pragma unroll
        for (int t = 0; t < 4; t++) {
            const int rb = (k0 + tig) * OXS + nb0 + t * 8 + gid;
            float bh0 = xhi[rb], bh1 = xhi[rb + 4 * OXS];
            float bl0 = xlo[rb], bl1 = xlo[rb + 4 * OXS];
            mma8(acc[t], ah0, ah1, ah2, ah3, bh0, bh1);
            mma8(acc[t], ah0, ah1, ah2, ah3, bl0, bl1);
            mma8(acc[t], al0, al1, al2, al3, bh0, bh1);
        }
    }

    const float bias0 = bps[m0 + gid];
    const float bias1 = bps[m0 + gid + 8];
    float* o0 = out + ((size_t)(b * CCH + m0 + gid    )) * NPIX + n0;
    float* o1 = out + ((size_t)(b * CCH + m0 + gid + 8)) * NPIX + n0;
    #pragma unroll
    for (int t = 0; t < 4; t++) {
        int nc = nb0 + t * 8 + 2 * tig;
        *(float2*)(o0 + nc) = make_float2(acc[t].x + bias0, acc[t].y + bias0);
        *(float2*)(o1 + nc) = make_float2(acc[t].z + bias1, acc[t].w + bias1);
    }

    __syncthreads();
    if (s_last) {
        for (int i = tid; i < CCH * CCH; i += 256) g_P[b * CCH * CCH + i] = 0.f;
        if (tid == 0) g_cntP[b] = 0u;
    }
}

// ---------------- launch ------------------------------------------------------
extern "C" void kernel_launch(void* const* d_in, const int* in_sizes, int n_in,
                              void* d_out, int out_size) {
    const float* x       = (const float*)d_in[0];
    const float* Wq      = (const float*)d_in[1];
    const float* Wk      = (const float*)d_in[2];
    const float* Wv      = (const float*)d_in[3];
    const float* Wp      = (const float*)d_in[4];
    const float* bp      = (const float*)d_in[5];
    const float* rescale = (const float*)d_in[6];

    float* out      = (float*)d_out;
    float* attn_out = out + (size_t)out_size - (size_t)BATCH * NHEADS * DHEAD * DHEAD;

    cudaFuncSetAttribute(gram_kernel, cudaFuncAttributeMaxDynamicSharedMemorySize, GRAM_SMEM);
    cudaFuncSetAttribute(attn_kernel, cudaFuncAttributeMaxDynamicSharedMemorySize, ATTN_SMEM);
    cudaFuncSetAttribute(out_kernel,  cudaFuncAttributeMaxDynamicSharedMemorySize, OUT_SMEM);

    gram_kernel<<<BATCH * 128, 256, GRAM_SMEM>>>(x);
    attn_kernel<<<BATCH * NHEADS, 256, ATTN_SMEM>>>(Wq, Wk, Wv, Wp, rescale, attn_out);
    out_kernel<<<BATCH * 256, 256, OUT_SMEM>>>(x, bp, out);
}